// round 10
// baseline (speedup 1.0000x reference)
#include <cuda_runtime.h>
#include <cuda_bf16.h>
#include <math.h>

#define BB 4096
#define IN_DIM 64
#define UU 256
#define NN 128
#define WW 64
#define OUT_DIM 64
#define NPH 70
#define PDIM 268   // 2*NPH + 2*W
#define CLIPV 20.0f
#define EPSV 1e-12f
#define KD 384     // GEMM1 K dim

// d_out layout (reference tuple order, each flattened):
#define O_OUT 0
#define O_RV  (BB*OUT_DIM)
#define O_WR  (O_RV + BB*WW)
#define O_WW  (O_WR + BB*NN)
#define O_M   (O_WW + BB*NN)
#define O_H   (O_M + (size_t)BB*NN*WW)
#define O_C   (O_H + (size_t)BB*UU)

__device__ float g_params[BB * PDIM];               // clipped head params
__device__ float g_z[(size_t)BB * 1024];            // raw LSTM pre-activations
__device__ float g_hWo[BB * 64];                    // h_new @ Wo_top (raw)
__device__ __nv_bfloat16 g_Ah[BB * KD], g_Al[BB * KD];      // activations hi/lo
__device__ __nv_bfloat16 g_Wh[1024 * KD], g_Wl[1024 * KD];  // weights^T hi/lo
__device__ __nv_bfloat16 g_Hh[BB * UU], g_Hl[BB * UU];      // h_new hi/lo
__device__ __nv_bfloat16 g_Wph[384 * UU], g_Wpl[384 * UU];  // [Wp|Wo_top]^T hi/lo

__device__ __forceinline__ float sigf(float x) { return 1.0f / (1.0f + expf(-x)); }
__device__ __forceinline__ float softplusf(float x) { return log1pf(expf(x)); }
__device__ __forceinline__ float clipf(float x) { return fminf(fmaxf(x, -CLIPV), CLIPV); }

__device__ __forceinline__ void mma16816(float* c, const unsigned* a,
                                         unsigned b0, unsigned b1) {
    asm volatile(
        "mma.sync.aligned.m16n8k16.row.col.f32.bf16.bf16.f32 "
        "{%0,%1,%2,%3}, {%4,%5,%6,%7}, {%8,%9}, {%0,%1,%2,%3};"
        : "+f"(c[0]), "+f"(c[1]), "+f"(c[2]), "+f"(c[3])
        : "r"(a[0]), "r"(a[1]), "r"(a[2]), "r"(a[3]), "r"(b0), "r"(b1));
}

__device__ __forceinline__ void ldsm4(unsigned* r, const void* p) {
    unsigned a = (unsigned)__cvta_generic_to_shared(p);
    asm volatile("ldmatrix.sync.aligned.m8n8.x4.shared.b16 {%0,%1,%2,%3}, [%4];"
        : "=r"(r[0]), "=r"(r[1]), "=r"(r[2]), "=r"(r[3]) : "r"(a));
}

__device__ __forceinline__ void cp16(void* dst_smem, const void* src_gmem) {
    unsigned d = (unsigned)__cvta_generic_to_shared(dst_smem);
    asm volatile("cp.async.cg.shared.global [%0], [%1], 16;\n" :: "r"(d), "l"(src_gmem));
}
#define CP_COMMIT() asm volatile("cp.async.commit_group;\n" ::: "memory")
#define CP_WAIT(n)  asm volatile("cp.async.wait_group %0;\n" :: "n"(n) : "memory")

// ---------------------------------------------------------------------------
// K0a: convert activations [x | rv0 | h0] -> g_Ah/g_Al
// ---------------------------------------------------------------------------
__global__ __launch_bounds__(1024) void k0_act(
    const float* __restrict__ x, const float* __restrict__ rv0,
    const float* __restrict__ h0)
{
    int idx = blockIdx.x * 1024 + threadIdx.x;
    int row = idx / KD, kk = idx - row * KD;
    float v;
    if (kk < 64)       v = x[row * 64 + kk];
    else if (kk < 128) v = rv0[row * 64 + (kk - 64)];
    else               v = h0[row * 256 + (kk - 128)];
    __nv_bfloat16 hi = __float2bfloat16(v);
    g_Ah[idx] = hi;
    g_Al[idx] = __float2bfloat16(v - __bfloat162float(hi));
}

// ---------------------------------------------------------------------------
// K0b: transpose + convert [Wk;Wr] (384x1024) -> g_Wh/g_Wl [1024][384]
// ---------------------------------------------------------------------------
__global__ __launch_bounds__(256) void k0_wt(
    const float* __restrict__ Wk, const float* __restrict__ Wr)
{
    __shared__ float t[32][33];
    int n0 = blockIdx.x * 32, k0 = blockIdx.y * 32;
    int tx = threadIdx.x & 31, ty = threadIdx.x >> 5;
#pragma unroll
    for (int i = 0; i < 32; i += 8) {
        int k = k0 + ty + i, n = n0 + tx;
        t[ty + i][tx] = (k < 128) ? Wk[k * 1024 + n] : Wr[(k - 128) * 1024 + n];
    }
    __syncthreads();
#pragma unroll
    for (int i = 0; i < 32; i += 8) {
        int n = n0 + ty + i, k = k0 + tx;
        float v = t[tx][ty + i];
        __nv_bfloat16 hi = __float2bfloat16(v);
        g_Wh[n * KD + k] = hi;
        g_Wl[n * KD + k] = __float2bfloat16(v - __bfloat162float(hi));
    }
}

// ---------------------------------------------------------------------------
// K0c: transpose + convert [Wp | Wo_top] (256 x (268|64)) -> g_Wph/g_Wpl
// cols 0..267 = Wp, 268..331 = Wo rows 0..255, 332..383 = 0
// ---------------------------------------------------------------------------
__global__ __launch_bounds__(256) void k0_wp(
    const float* __restrict__ Wp, const float* __restrict__ Wo)
{
    __shared__ float t[32][33];
    int n0 = blockIdx.x * 32, k0 = blockIdx.y * 32;
    int tx = threadIdx.x & 31, ty = threadIdx.x >> 5;
#pragma unroll
    for (int i = 0; i < 32; i += 8) {
        int k = k0 + ty + i, n = n0 + tx;
        float v = 0.0f;
        if (n < PDIM)      v = Wp[k * PDIM + n];
        else if (n < 332)  v = Wo[k * 64 + (n - PDIM)];
        t[ty + i][tx] = v;
    }
    __syncthreads();
#pragma unroll
    for (int i = 0; i < 32; i += 8) {
        int n = n0 + ty + i, k = k0 + tx;
        float v = t[tx][ty + i];
        __nv_bfloat16 hi = __float2bfloat16(v);
        g_Wph[n * UU + k] = hi;
        g_Wpl[n * UU + k] = __float2bfloat16(v - __bfloat162float(hi));
    }
}

// ---------------------------------------------------------------------------
// K1: z = A @ W^T -> g_z.  bf16 3-pass split MMA, cp.async + ldmatrix.
// ---------------------------------------------------------------------------
#define LDK 24

__global__ __launch_bounds__(256, 2) void k1_gemm()
{
    __shared__ __align__(16) __nv_bfloat16 smem[2 * 4 * 128 * LDK];   // 48KB
    const int tid = threadIdx.x;
    const int m0 = blockIdx.x * 128, n0 = blockIdx.y * 128;
    const int lane = tid & 31, wid = tid >> 5;
    const int wm = wid & 1, wn = wid >> 1;
    const int g = lane >> 2, t = lane & 3;
    const int lrow = lane & 15, lseg = (lane >> 4) << 3;   // ldmatrix addressing

    float acc[4][4][4];
#pragma unroll
    for (int mi = 0; mi < 4; mi++)
#pragma unroll
        for (int nj = 0; nj < 4; nj++)
#pragma unroll
            for (int q = 0; q < 4; q++) acc[mi][nj][q] = 0.0f;

    const int row = tid >> 1, seg = tid & 1;
    const int soff = row * LDK + seg * 8;
    const int goffA = (m0 + row) * KD + seg * 8;
    const int goffB = (n0 + row) * KD + seg * 8;

    auto issue = [&](int s, int kb) {
        __nv_bfloat16* base = smem + s * (4 * 128 * LDK);
        cp16(base + 0 * 128 * LDK + soff, g_Ah + goffA + kb);
        cp16(base + 1 * 128 * LDK + soff, g_Al + goffA + kb);
        cp16(base + 2 * 128 * LDK + soff, g_Wh + goffB + kb);
        cp16(base + 3 * 128 * LDK + soff, g_Wl + goffB + kb);
        CP_COMMIT();
    };

    issue(0, 0);

    for (int it = 0; it < 24; it++) {
        if (it < 23) { issue((it + 1) & 1, 16 * (it + 1)); CP_WAIT(1); }
        else         { CP_WAIT(0); }
        __syncthreads();

        const __nv_bfloat16* Ah = smem + (it & 1) * (4 * 128 * LDK);
        const __nv_bfloat16* Al = Ah + 128 * LDK;
        const __nv_bfloat16* Bh = Ah + 2 * 128 * LDK;
        const __nv_bfloat16* Bl = Ah + 3 * 128 * LDK;

        unsigned af[4][4], bh[2][4], bl[2][4];
#pragma unroll
        for (int mi = 0; mi < 4; mi++)
            ldsm4(af[mi], &Ah[(wm * 64 + mi * 16 + lrow) * LDK + lseg]);
#pragma unroll
        for (int pr = 0; pr < 2; pr++) {
            int cb = (wn * 32 + pr * 16 + lrow) * LDK + lseg;
            ldsm4(bh[pr], &Bh[cb]);
            ldsm4(bl[pr], &Bl[cb]);
        }
#pragma unroll
        for (int nj = 0; nj < 4; nj++) {            // Ah * Wh
            unsigned b0 = bh[nj >> 1][nj & 1], b1 = bh[nj >> 1][2 + (nj & 1)];
#pragma unroll
            for (int mi = 0; mi < 4; mi++) mma16816(acc[mi][nj], af[mi], b0, b1);
        }
#pragma unroll
        for (int nj = 0; nj < 4; nj++) {            // Ah * Wl
            unsigned b0 = bl[nj >> 1][nj & 1], b1 = bl[nj >> 1][2 + (nj & 1)];
#pragma unroll
            for (int mi = 0; mi < 4; mi++) mma16816(acc[mi][nj], af[mi], b0, b1);
        }
#pragma unroll
        for (int mi = 0; mi < 4; mi++)              // Al fragments
            ldsm4(af[mi], &Al[(wm * 64 + mi * 16 + lrow) * LDK + lseg]);
#pragma unroll
        for (int nj = 0; nj < 4; nj++) {            // Al * Wh
            unsigned b0 = bh[nj >> 1][nj & 1], b1 = bh[nj >> 1][2 + (nj & 1)];
#pragma unroll
            for (int mi = 0; mi < 4; mi++) mma16816(acc[mi][nj], af[mi], b0, b1);
        }
        __syncthreads();
    }

#pragma unroll
    for (int mi = 0; mi < 4; mi++)
#pragma unroll
        for (int nj = 0; nj < 4; nj++) {
            int r = m0 + wm * 64 + mi * 16 + g;
            int col = n0 + wn * 32 + nj * 8 + 2 * t;
            *(float2*)&g_z[(size_t)r * 1024 + col] =
                make_float2(acc[mi][nj][0], acc[mi][nj][1]);
            *(float2*)&g_z[(size_t)(r + 8) * 1024 + col] =
                make_float2(acc[mi][nj][2], acc[mi][nj][3]);
        }
}

// ---------------------------------------------------------------------------
// K2a: LSTM gate epilogue -> h_new/c_new (d_out) + bf16 split of h
// ---------------------------------------------------------------------------
__global__ __launch_bounds__(1024) void k2a_gates(
    const float* __restrict__ c0, const float* __restrict__ bl,
    float* __restrict__ out)
{
    int idx = blockIdx.x * 1024 + threadIdx.x;    // row*256 + u
    int row = idx >> 8, u = idx & 255;
    const float* zr = g_z + (size_t)row * 1024 + u;
    float zi = zr[0]   + bl[u];
    float zf = zr[256] + bl[256 + u];
    float zg = zr[512] + bl[512 + u];
    float zo = zr[768] + bl[768 + u];
    float cn = sigf(zf) * c0[idx] + sigf(zi) * tanhf(zg);
    float hn = sigf(zo) * tanhf(cn);
    out[O_C + idx] = cn;
    out[O_H + idx] = hn;
    __nv_bfloat16 hi = __float2bfloat16(hn);
    g_Hh[idx] = hi;
    g_Hl[idx] = __float2bfloat16(hn - __bfloat162float(hi));
}

// ---------------------------------------------------------------------------
// K2b: [params | hWo] = h @ [Wp|Wo_top] ; params clipped+biased, hWo raw.
// ---------------------------------------------------------------------------
__global__ __launch_bounds__(256, 2) void k2b_gemm(const float* __restrict__ bp)
{
    __shared__ __align__(16) __nv_bfloat16 smem[2 * 4 * 128 * LDK];
    const int tid = threadIdx.x;
    const int m0 = blockIdx.x * 128, n0 = blockIdx.y * 128;
    const int lane = tid & 31, wid = tid >> 5;
    const int wm = wid & 1, wn = wid >> 1;
    const int g = lane >> 2, t = lane & 3;
    const int lrow = lane & 15, lseg = (lane >> 4) << 3;

    float acc[4][4][4];
#pragma unroll
    for (int mi = 0; mi < 4; mi++)
#pragma unroll
        for (int nj = 0; nj < 4; nj++)
#pragma unroll
            for (int q = 0; q < 4; q++) acc[mi][nj][q] = 0.0f;

    const int row = tid >> 1, seg = tid & 1;
    const int soff = row * LDK + seg * 8;
    const int goffA = (m0 + row) * UU + seg * 8;
    const int goffB = (n0 + row) * UU + seg * 8;

    auto issue = [&](int s, int kb) {
        __nv_bfloat16* base = smem + s * (4 * 128 * LDK);
        cp16(base + 0 * 128 * LDK + soff, g_Hh + goffA + kb);
        cp16(base + 1 * 128 * LDK + soff, g_Hl + goffA + kb);
        cp16(base + 2 * 128 * LDK + soff, g_Wph + goffB + kb);
        cp16(base + 3 * 128 * LDK + soff, g_Wpl + goffB + kb);
        CP_COMMIT();
    };

    issue(0, 0);

    for (int it = 0; it < 16; it++) {
        if (it < 15) { issue((it + 1) & 1, 16 * (it + 1)); CP_WAIT(1); }
        else         { CP_WAIT(0); }
        __syncthreads();

        const __nv_bfloat16* Ah = smem + (it & 1) * (4 * 128 * LDK);
        const __nv_bfloat16* Al = Ah + 128 * LDK;
        const __nv_bfloat16* Bh = Ah + 2 * 128 * LDK;
        const __nv_bfloat16* Bl = Ah + 3 * 128 * LDK;

        unsigned af[4][4], bh[2][4], bl[2][4];
#pragma unroll
        for (int mi = 0; mi < 4; mi++)
            ldsm4(af[mi], &Ah[(wm * 64 + mi * 16 + lrow) * LDK + lseg]);
#pragma unroll
        for (int pr = 0; pr < 2; pr++) {
            int cb = (wn * 32 + pr * 16 + lrow) * LDK + lseg;
            ldsm4(bh[pr], &Bh[cb]);
            ldsm4(bl[pr], &Bl[cb]);
        }
#pragma unroll
        for (int nj = 0; nj < 4; nj++) {
            unsigned b0 = bh[nj >> 1][nj & 1], b1 = bh[nj >> 1][2 + (nj & 1)];
#pragma unroll
            for (int mi = 0; mi < 4; mi++) mma16816(acc[mi][nj], af[mi], b0, b1);
        }
#pragma unroll
        for (int nj = 0; nj < 4; nj++) {
            unsigned b0 = bl[nj >> 1][nj & 1], b1 = bl[nj >> 1][2 + (nj & 1)];
#pragma unroll
            for (int mi = 0; mi < 4; mi++) mma16816(acc[mi][nj], af[mi], b0, b1);
        }
#pragma unroll
        for (int mi = 0; mi < 4; mi++)
            ldsm4(af[mi], &Al[(wm * 64 + mi * 16 + lrow) * LDK + lseg]);
#pragma unroll
        for (int nj = 0; nj < 4; nj++) {
            unsigned b0 = bh[nj >> 1][nj & 1], b1 = bh[nj >> 1][2 + (nj & 1)];
#pragma unroll
            for (int mi = 0; mi < 4; mi++) mma16816(acc[mi][nj], af[mi], b0, b1);
        }
        __syncthreads();
    }

#pragma unroll
    for (int mi = 0; mi < 4; mi++)
#pragma unroll
        for (int nj = 0; nj < 4; nj++) {
            int col = n0 + wn * 32 + nj * 8 + 2 * t;
            int r = m0 + wm * 64 + mi * 16 + g;
            if (col < PDIM) {            // col even, PDIM even -> col+1 < PDIM
                float b0v = bp[col], b1v = bp[col + 1];
                *(float2*)&g_params[r * PDIM + col] = make_float2(
                    clipf(acc[mi][nj][0] + b0v), clipf(acc[mi][nj][1] + b1v));
                *(float2*)&g_params[(r + 8) * PDIM + col] = make_float2(
                    clipf(acc[mi][nj][2] + b0v), clipf(acc[mi][nj][3] + b1v));
            } else if (col < 332) {      // h @ Wo_top, raw
                int cc = col - PDIM;
                *(float2*)&g_hWo[r * 64 + cc] =
                    make_float2(acc[mi][nj][0], acc[mi][nj][1]);
                *(float2*)&g_hWo[(r + 8) * 64 + cc] =
                    make_float2(acc[mi][nj][2], acc[mi][nj][3]);
            }
        }
}

// ---------------------------------------------------------------------------
// K3: per-sample addressing, both heads in parallel (256 thr: tid<128 read
// head, tid>=128 write head) + read_vec + memory update. No softmax max-pass:
// |beta * cos| <= softplus(20) ~ 20 -> exp safe in fp32.
// ---------------------------------------------------------------------------
__global__ __launch_bounds__(256) void k3_addr(
    const float* __restrict__ M,
    const float* __restrict__ w0p, const float* __restrict__ w1p,
    float* __restrict__ out)
{
    __shared__ float Ms[128 * 65];
    __shared__ float psm[PDIM];
    __shared__ float ks[2][64], er[64], ad[64];
    __shared__ float wgs[2][128], wrs[128], wws[128];
    __shared__ float reds[2][4], redp[2][4];
    __shared__ float part[256];

    int b = blockIdx.x, tid = threadIdx.x;
    int h = tid >> 7, n = tid & 127;
    int lane = tid & 31, wid = tid >> 5, hw = wid & 3;

    const float4* M4 = (const float4*)(M + (size_t)b * NN * WW);
#pragma unroll
    for (int t = 0; t < 8; t++) {
        int idx4 = tid + t * 256;
        float4 v = M4[idx4];
        int r = idx4 >> 4, w0 = (idx4 & 15) * 4;
        float* p = &Ms[r * 65 + w0];
        p[0] = v.x; p[1] = v.y; p[2] = v.z; p[3] = v.w;
    }
    for (int i = tid; i < PDIM; i += 256) psm[i] = g_params[b * PDIM + i];
    __syncthreads();

    float s = 0.0f;
#pragma unroll
    for (int w = 0; w < 64; w++) { float m = Ms[n * 65 + w]; s += m * m; }
    float minv = rsqrtf(fmaxf(s, EPSV));

    if (tid < 64)                      er[tid] = sigf(psm[2 * NPH + tid]);
    else if (tid >= 128 && tid < 192)  ad[tid - 128] = tanhf(psm[2 * NPH + 64 + (tid - 128)]);

    int off = h * NPH;
    if (n < 64) ks[h][n] = tanhf(psm[off + n]);
    __syncthreads();

    float sk = 0.0f;
#pragma unroll
    for (int w = 0; w < 64; w++) sk += ks[h][w] * ks[h][w];
    float kninv = rsqrtf(fmaxf(sk, EPSV));
    float beta = softplusf(psm[off + 64]);
    float g = sigf(psm[off + 65]);
    float e0 = psm[off + 66], e1 = psm[off + 67], e2 = psm[off + 68];
    float mx3 = fmaxf(e0, fmaxf(e1, e2));
    float x0 = expf(e0 - mx3), x1 = expf(e1 - mx3), x2 = expf(e2 - mx3);
    float sinv = 1.0f / (x0 + x1 + x2);
    float s0 = x0 * sinv, s1 = x1 * sinv, s2 = x2 * sinv;
    float gamma = softplusf(psm[off + 69]) + 1.0f;

    float dot = 0.0f;
#pragma unroll
    for (int w = 0; w < 64; w++) dot += ks[h][w] * Ms[n * 65 + w];
    float v = beta * (-dot * kninv * minv);

    float e = expf(v);
    float ssum = e;
#pragma unroll
    for (int o = 16; o; o >>= 1) ssum += __shfl_xor_sync(0xffffffffu, ssum, o);
    if (lane == 0) reds[h][hw] = ssum;
    __syncthreads();
    ssum = reds[h][0] + reds[h][1] + reds[h][2] + reds[h][3];
    float wc = e / ssum;

    const float* prev = h ? w1p : w0p;
    float wg = g * wc + (1.0f - g) * prev[b * 128 + n];
    wgs[h][n] = wg;
    __syncthreads();

    float w_ = s0 * wg + s1 * wgs[h][(n + 127) & 127] + s2 * wgs[h][(n + 1) & 127];
    float wsh = exp2f(gamma * log2f(w_));    // w_ >= 0; w_==0 -> 0
    float s2sum = wsh;
#pragma unroll
    for (int o = 16; o; o >>= 1) s2sum += __shfl_xor_sync(0xffffffffu, s2sum, o);
    if (lane == 0) redp[h][hw] = s2sum;
    __syncthreads();
    s2sum = redp[h][0] + redp[h][1] + redp[h][2] + redp[h][3];
    float wf = wsh / s2sum;

    if (h == 0) { wrs[n] = wf; out[O_WR + (size_t)b * 128 + n] = wf; }
    else        { wws[n] = wf; out[O_WW + (size_t)b * 128 + n] = wf; }
    __syncthreads();

    // read_vec: 4-way split over n
    {
        int w = tid & 63, q = tid >> 6;
        float r = 0.0f;
#pragma unroll
        for (int i = 0; i < 32; i++) {
            int nn = q * 32 + i;
            r += wrs[nn] * Ms[nn * 65 + w];
        }
        part[tid] = r;
        __syncthreads();
        if (tid < 64)
            out[O_RV + (size_t)b * 64 + tid] =
                part[tid] + part[64 + tid] + part[128 + tid] + part[192 + tid];
    }

    // M update
    float4* Mo = (float4*)(out + O_M + (size_t)b * NN * WW);
#pragma unroll
    for (int t = 0; t < 8; t++) {
        int idx4 = tid + t * 256;
        int r = idx4 >> 4, w0 = (idx4 & 15) * 4;
        float wn = wws[r];
        const float* p = &Ms[r * 65 + w0];
        float4 v4;
        v4.x = p[0] * (1.0f - wn * er[w0 + 0]) + wn * ad[w0 + 0];
        v4.y = p[1] * (1.0f - wn * er[w0 + 1]) + wn * ad[w0 + 1];
        v4.z = p[2] * (1.0f - wn * er[w0 + 2]) + wn * ad[w0 + 2];
        v4.w = p[3] * (1.0f - wn * er[w0 + 3]) + wn * ad[w0 + 3];
        Mo[idx4] = v4;
    }
}

// ---------------------------------------------------------------------------
// K4: out = clip(g_hWo + rv @ Wo_bot + bo).  16 rows/CTA, K=64 only.
// ---------------------------------------------------------------------------
__global__ __launch_bounds__(256) void k4_out(
    const float* __restrict__ Wo, const float* __restrict__ bo,
    float* __restrict__ out)
{
    __shared__ float rvs[16 * 64];
    int tid = threadIdx.x;
    int row0 = blockIdx.x * 16;

    for (int i = tid; i < 16 * 64; i += 256)
        rvs[i] = out[O_RV + (size_t)row0 * 64 + i];
    __syncthreads();

    int c = tid & 63, rg = tid >> 6;     // rg handles rows rg*4 .. rg*4+3
    float acc[4] = {0.0f, 0.0f, 0.0f, 0.0f};
    for (int k = 0; k < 64; k++) {
        float wv = __ldg(&Wo[(256 + k) * 64 + c]);
#pragma unroll
        for (int j = 0; j < 4; j++)
            acc[j] += rvs[(rg * 4 + j) * 64 + k] * wv;
    }
    float bv = bo[c];
#pragma unroll
    for (int j = 0; j < 4; j++) {
        int r = row0 + rg * 4 + j;
        out[O_OUT + (size_t)r * 64 + c] = clipf(acc[j] + g_hWo[r * 64 + c] + bv);
    }
}

// ---------------------------------------------------------------------------
extern "C" void kernel_launch(void* const* d_in, const int* in_sizes, int n_in,
                              void* d_out, int out_size)
{
    const float* x   = (const float*)d_in[0];
    const float* h0  = (const float*)d_in[1];
    const float* c0  = (const float*)d_in[2];
    const float* rv0 = (const float*)d_in[3];
    const float* w0p = (const float*)d_in[4];
    const float* w1p = (const float*)d_in[5];
    const float* M   = (const float*)d_in[6];
    const float* Wk  = (const float*)d_in[7];
    const float* Wr  = (const float*)d_in[8];
    const float* bl  = (const float*)d_in[9];
    const float* Wp  = (const float*)d_in[10];
    const float* bp  = (const float*)d_in[11];
    const float* Wo  = (const float*)d_in[12];
    const float* bo  = (const float*)d_in[13];
    float* out = (float*)d_out;

    k0_act<<<BB * KD / 1024, 1024>>>(x, rv0, h0);
    k0_wt<<<dim3(32, 12), 256>>>(Wk, Wr);
    k0_wp<<<dim3(12, 8), 256>>>(Wp, Wo);
    k1_gemm<<<dim3(32, 8), 256>>>();
    k2a_gates<<<BB * UU / 1024, 1024>>>(c0, bl, out);
    k2b_gemm<<<dim3(32, 3), 256>>>(bp);
    k3_addr<<<BB, 256>>>(M, w0p, w1p, out);
    k4_out<<<BB / 16, 256>>>(Wo, bo, out);
}

// round 16
// speedup vs baseline: 1.0716x; 1.0716x over previous
#include <cuda_runtime.h>
#include <cuda_bf16.h>
#include <math.h>
#include <cstdint>

#define BB 4096
#define IN_DIM 64
#define UU 256
#define NN 128
#define WW 64
#define OUT_DIM 64
#define NPH 70
#define PDIM 268   // 2*NPH + 2*W
#define CLIPV 20.0f
#define EPSV 1e-12f
#define KD 384     // GEMM1 K dim

// d_out layout (reference tuple order, each flattened):
#define O_OUT 0
#define O_RV  (BB*OUT_DIM)
#define O_WR  (O_RV + BB*WW)
#define O_WW  (O_WR + BB*NN)
#define O_M   (O_WW + BB*NN)
#define O_H   (O_M + (size_t)BB*NN*WW)
#define O_C   (O_H + (size_t)BB*UU)

__device__ float g_params[BB * PDIM];               // clipped head params
__device__ float g_z[(size_t)BB * 1024];            // raw LSTM pre-activations
__device__ float g_hWo[BB * 64];                    // h_new @ Wo_top (raw)
__device__ __nv_bfloat16 g_Ah[BB * KD], g_Al[BB * KD];      // activations hi/lo
__device__ __nv_bfloat16 g_Wh[1024 * KD], g_Wl[1024 * KD];  // weights^T hi/lo
__device__ __nv_bfloat16 g_Hh[BB * UU], g_Hl[BB * UU];      // h_new hi/lo
__device__ __nv_bfloat16 g_Wph[384 * UU], g_Wpl[384 * UU];  // [Wp|Wo_top]^T hi/lo

__device__ __forceinline__ float sigf(float x) { return 1.0f / (1.0f + expf(-x)); }
__device__ __forceinline__ float softplusf(float x) { return log1pf(expf(x)); }
__device__ __forceinline__ float clipf(float x) { return fminf(fmaxf(x, -CLIPV), CLIPV); }

__device__ __forceinline__ void mma16816(float* c, const unsigned* a,
                                         unsigned b0, unsigned b1) {
    asm volatile(
        "mma.sync.aligned.m16n8k16.row.col.f32.bf16.bf16.f32 "
        "{%0,%1,%2,%3}, {%4,%5,%6,%7}, {%8,%9}, {%0,%1,%2,%3};"
        : "+f"(c[0]), "+f"(c[1]), "+f"(c[2]), "+f"(c[3])
        : "r"(a[0]), "r"(a[1]), "r"(a[2]), "r"(a[3]), "r"(b0), "r"(b1));
}

__device__ __forceinline__ void cp16(void* dst_smem, const void* src_gmem) {
    unsigned d = (unsigned)__cvta_generic_to_shared(dst_smem);
    asm volatile("cp.async.cg.shared.global [%0], [%1], 16;\n" :: "r"(d), "l"(src_gmem));
}
#define CP_COMMIT() asm volatile("cp.async.commit_group;\n" ::: "memory")
#define CP_WAIT(n)  asm volatile("cp.async.wait_group %0;\n" :: "n"(n) : "memory")

// ---------------------------------------------------------------------------
// K0a: convert activations [x | rv0 | h0] -> g_Ah/g_Al
// ---------------------------------------------------------------------------
__global__ __launch_bounds__(1024) void k0_act(
    const float* __restrict__ x, const float* __restrict__ rv0,
    const float* __restrict__ h0)
{
    int idx = blockIdx.x * 1024 + threadIdx.x;
    int row = idx / KD, kk = idx - row * KD;
    float v;
    if (kk < 64)       v = x[row * 64 + kk];
    else if (kk < 128) v = rv0[row * 64 + (kk - 64)];
    else               v = h0[row * 256 + (kk - 128)];
    __nv_bfloat16 hi = __float2bfloat16(v);
    g_Ah[idx] = hi;
    g_Al[idx] = __float2bfloat16(v - __bfloat162float(hi));
}

// ---------------------------------------------------------------------------
// K0b: transpose + convert [Wk;Wr] (384x1024) -> g_Wh/g_Wl [1024][384]
// ---------------------------------------------------------------------------
__global__ __launch_bounds__(256) void k0_wt(
    const float* __restrict__ Wk, const float* __restrict__ Wr)
{
    __shared__ float t[32][33];
    int n0 = blockIdx.x * 32, k0 = blockIdx.y * 32;
    int tx = threadIdx.x & 31, ty = threadIdx.x >> 5;
#pragma unroll
    for (int i = 0; i < 32; i += 8) {
        int k = k0 + ty + i, n = n0 + tx;
        t[ty + i][tx] = (k < 128) ? Wk[k * 1024 + n] : Wr[(k - 128) * 1024 + n];
    }
    __syncthreads();
#pragma unroll
    for (int i = 0; i < 32; i += 8) {
        int n = n0 + ty + i, k = k0 + tx;
        float v = t[tx][ty + i];
        __nv_bfloat16 hi = __float2bfloat16(v);
        g_Wh[n * KD + k] = hi;
        g_Wl[n * KD + k] = __float2bfloat16(v - __bfloat162float(hi));
    }
}

// ---------------------------------------------------------------------------
// K0c: transpose + convert [Wp | Wo_top] -> g_Wph/g_Wpl (cols 332..383 = 0)
// ---------------------------------------------------------------------------
__global__ __launch_bounds__(256) void k0_wp(
    const float* __restrict__ Wp, const float* __restrict__ Wo)
{
    __shared__ float t[32][33];
    int n0 = blockIdx.x * 32, k0 = blockIdx.y * 32;
    int tx = threadIdx.x & 31, ty = threadIdx.x >> 5;
#pragma unroll
    for (int i = 0; i < 32; i += 8) {
        int k = k0 + ty + i, n = n0 + tx;
        float v = 0.0f;
        if (n < PDIM)      v = Wp[k * PDIM + n];
        else if (n < 332)  v = Wo[k * 64 + (n - PDIM)];
        t[ty + i][tx] = v;
    }
    __syncthreads();
#pragma unroll
    for (int i = 0; i < 32; i += 8) {
        int n = n0 + ty + i, k = k0 + tx;
        float v = t[tx][ty + i];
        __nv_bfloat16 hi = __float2bfloat16(v);
        g_Wph[n * UU + k] = hi;
        g_Wpl[n * UU + k] = __float2bfloat16(v - __bfloat162float(hi));
    }
}

// ---------------------------------------------------------------------------
// K1: z = A @ W^T -> g_z.  bf16 3-pass split HMMA (scalar fragment loads),
// cp.async double-buffered, ONE sync per k-chunk.
// ---------------------------------------------------------------------------
#define LDK 24   // padded bf16 k-stride: fragment bank = (12g+t)%32, a permutation

__global__ __launch_bounds__(256, 2) void k1_gemm()
{
    __shared__ __nv_bfloat16 smem[2 * 4 * 128 * LDK];   // 48KB
    const int tid = threadIdx.x;
    const int m0 = blockIdx.x * 128, n0 = blockIdx.y * 128;
    const int lane = tid & 31, wid = tid >> 5;
    const int wm = wid & 1, wn = wid >> 1;
    const int g = lane >> 2, t = lane & 3;

    float acc[4][4][4];
#pragma unroll
    for (int mi = 0; mi < 4; mi++)
#pragma unroll
        for (int nj = 0; nj < 4; nj++)
#pragma unroll
            for (int q = 0; q < 4; q++) acc[mi][nj][q] = 0.0f;

    const int row = tid >> 1, seg = tid & 1;
    const int soff = row * LDK + seg * 8;
    const int goffA = (m0 + row) * KD + seg * 8;
    const int goffB = (n0 + row) * KD + seg * 8;

    auto issue = [&](int s, int kb) {
        __nv_bfloat16* base = smem + s * (4 * 128 * LDK);
        cp16(base + 0 * 128 * LDK + soff, g_Ah + goffA + kb);
        cp16(base + 1 * 128 * LDK + soff, g_Al + goffA + kb);
        cp16(base + 2 * 128 * LDK + soff, g_Wh + goffB + kb);
        cp16(base + 3 * 128 * LDK + soff, g_Wl + goffB + kb);
        CP_COMMIT();
    };

    issue(0, 0);

    for (int it = 0; it < 24; it++) {
        CP_WAIT(0);                 // current stage loaded
        __syncthreads();            // + previous compute done (protects other stage)
        if (it < 23) issue((it + 1) & 1, 16 * (it + 1));   // overlaps compute below

        const __nv_bfloat16* Ah = smem + (it & 1) * (4 * 128 * LDK);
        const __nv_bfloat16* Al = Ah + 128 * LDK;
        const __nv_bfloat16* Bh = Ah + 2 * 128 * LDK;
        const __nv_bfloat16* Bl = Ah + 3 * 128 * LDK;

        unsigned af[4][4];
#pragma unroll
        for (int mi = 0; mi < 4; mi++) {
            int rb = wm * 64 + mi * 16;
            af[mi][0] = *(const unsigned*)&Ah[(rb + g) * LDK + 2 * t];
            af[mi][1] = *(const unsigned*)&Ah[(rb + g + 8) * LDK + 2 * t];
            af[mi][2] = *(const unsigned*)&Ah[(rb + g) * LDK + 2 * t + 8];
            af[mi][3] = *(const unsigned*)&Ah[(rb + g + 8) * LDK + 2 * t + 8];
        }
#pragma unroll
        for (int nj = 0; nj < 4; nj++) {            // Ah * Wh
            int cb = wn * 32 + nj * 8 + g;
            unsigned b0 = *(const unsigned*)&Bh[cb * LDK + 2 * t];
            unsigned b1 = *(const unsigned*)&Bh[cb * LDK + 2 * t + 8];
#pragma unroll
            for (int mi = 0; mi < 4; mi++) mma16816(acc[mi][nj], af[mi], b0, b1);
        }
#pragma unroll
        for (int nj = 0; nj < 4; nj++) {            // Ah * Wl
            int cb = wn * 32 + nj * 8 + g;
            unsigned b0 = *(const unsigned*)&Bl[cb * LDK + 2 * t];
            unsigned b1 = *(const unsigned*)&Bl[cb * LDK + 2 * t + 8];
#pragma unroll
            for (int mi = 0; mi < 4; mi++) mma16816(acc[mi][nj], af[mi], b0, b1);
        }
#pragma unroll
        for (int mi = 0; mi < 4; mi++) {            // Al fragments
            int rb = wm * 64 + mi * 16;
            af[mi][0] = *(const unsigned*)&Al[(rb + g) * LDK + 2 * t];
            af[mi][1] = *(const unsigned*)&Al[(rb + g + 8) * LDK + 2 * t];
            af[mi][2] = *(const unsigned*)&Al[(rb + g) * LDK + 2 * t + 8];
            af[mi][3] = *(const unsigned*)&Al[(rb + g + 8) * LDK + 2 * t + 8];
        }
#pragma unroll
        for (int nj = 0; nj < 4; nj++) {            // Al * Wh
            int cb = wn * 32 + nj * 8 + g;
            unsigned b0 = *(const unsigned*)&Bh[cb * LDK + 2 * t];
            unsigned b1 = *(const unsigned*)&Bh[cb * LDK + 2 * t + 8];
#pragma unroll
            for (int mi = 0; mi < 4; mi++) mma16816(acc[mi][nj], af[mi], b0, b1);
        }
    }

#pragma unroll
    for (int mi = 0; mi < 4; mi++)
#pragma unroll
        for (int nj = 0; nj < 4; nj++) {
            int r = m0 + wm * 64 + mi * 16 + g;
            int col = n0 + wn * 32 + nj * 8 + 2 * t;
            *(float2*)&g_z[(size_t)r * 1024 + col] =
                make_float2(acc[mi][nj][0], acc[mi][nj][1]);
            *(float2*)&g_z[(size_t)(r + 8) * 1024 + col] =
                make_float2(acc[mi][nj][2], acc[mi][nj][3]);
        }
}

// ---------------------------------------------------------------------------
// K2a: LSTM gate epilogue -> h_new/c_new (d_out) + bf16 split of h
// ---------------------------------------------------------------------------
__global__ __launch_bounds__(1024) void k2a_gates(
    const float* __restrict__ c0, const float* __restrict__ bl,
    float* __restrict__ out)
{
    int idx = blockIdx.x * 1024 + threadIdx.x;    // row*256 + u
    int row = idx >> 8, u = idx & 255;
    const float* zr = g_z + (size_t)row * 1024 + u;
    float zi = zr[0]   + bl[u];
    float zf = zr[256] + bl[256 + u];
    float zg = zr[512] + bl[512 + u];
    float zo = zr[768] + bl[768 + u];
    float cn = sigf(zf) * c0[idx] + sigf(zi) * tanhf(zg);
    float hn = sigf(zo) * tanhf(cn);
    out[O_C + idx] = cn;
    out[O_H + idx] = hn;
    __nv_bfloat16 hi = __float2bfloat16(hn);
    g_Hh[idx] = hi;
    g_Hl[idx] = __float2bfloat16(hn - __bfloat162float(hi));
}

// ---------------------------------------------------------------------------
// K2b: [params | hWo] = h @ [Wp|Wo_top].  64-row CTA tiles -> grid (64,3)
// = 192 CTAs (was 96: a third of the chip sat idle). Warp tile 32x32.
// ---------------------------------------------------------------------------
#define A2 (64 * LDK)
#define B2 (128 * LDK)
#define STG2 (2 * A2 + 2 * B2)

__global__ __launch_bounds__(256, 2) void k2b_gemm(const float* __restrict__ bp)
{
    __shared__ __nv_bfloat16 smem[2 * STG2];   // 36KB
    const int tid = threadIdx.x;
    const int m0 = blockIdx.x * 64, n0 = blockIdx.y * 128;
    const int lane = tid & 31, wid = tid >> 5;
    const int wm = wid & 1, wn = wid >> 1;
    const int g = lane >> 2, t = lane & 3;

    float acc[2][4][4];
#pragma unroll
    for (int mi = 0; mi < 2; mi++)
#pragma unroll
        for (int nj = 0; nj < 4; nj++)
#pragma unroll
            for (int q = 0; q < 4; q++) acc[mi][nj][q] = 0.0f;

    const int t2 = tid & 127;
    const int ar = t2 >> 1, as = t2 & 1;
    const int br = tid >> 1, bs = tid & 1;

    auto issue = [&](int s, int kb) {
        __nv_bfloat16* base = smem + s * STG2;
        const __nv_bfloat16* Asrc = (tid < 128) ? g_Hh : g_Hl;
        __nv_bfloat16* Adst = base + ((tid < 128) ? 0 : A2);
        cp16(Adst + ar * LDK + as * 8, Asrc + (m0 + ar) * UU + kb + as * 8);
        cp16(base + 2 * A2 + br * LDK + bs * 8, g_Wph + (n0 + br) * UU + kb + bs * 8);
        cp16(base + 2 * A2 + B2 + br * LDK + bs * 8, g_Wpl + (n0 + br) * UU + kb + bs * 8);
        CP_COMMIT();
    };

    issue(0, 0);

    for (int it = 0; it < 16; it++) {
        CP_WAIT(0);
        __syncthreads();
        if (it < 15) issue((it + 1) & 1, 16 * (it + 1));

        const __nv_bfloat16* Ah = smem + (it & 1) * STG2;
        const __nv_bfloat16* Al = Ah + A2;
        const __nv_bfloat16* Bh = Ah + 2 * A2;
        const __nv_bfloat16* Bl = Ah + 2 * A2 + B2;

        unsigned af[2][4];
#pragma unroll
        for (int mi = 0; mi < 2; mi++) {
            int rb = wm * 32 + mi * 16;
            af[mi][0] = *(const unsigned*)&Ah[(rb + g) * LDK + 2 * t];
            af[mi][1] = *(const unsigned*)&Ah[(rb + g + 8) * LDK + 2 * t];
            af[mi][2] = *(const unsigned*)&Ah[(rb + g) * LDK + 2 * t + 8];
            af[mi][3] = *(const unsigned*)&Ah[(rb + g + 8) * LDK + 2 * t + 8];
        }
#pragma unroll
        for (int nj = 0; nj < 4; nj++) {            // Ah * Wh
            int cb = wn * 32 + nj * 8 + g;
            unsigned b0 = *(const unsigned*)&Bh[cb * LDK + 2 * t];
            unsigned b1 = *(const unsigned*)&Bh[cb * LDK + 2 * t + 8];
#pragma unroll
            for (int mi = 0; mi < 2; mi++) mma16816(acc[mi][nj], af[mi], b0, b1);
        }
#pragma unroll
        for (int nj = 0; nj < 4; nj++) {            // Ah * Wl
            int cb = wn * 32 + nj * 8 + g;
            unsigned b0 = *(const unsigned*)&Bl[cb * LDK + 2 * t];
            unsigned b1 = *(const unsigned*)&Bl[cb * LDK + 2 * t + 8];
#pragma unroll
            for (int mi = 0; mi < 2; mi++) mma16816(acc[mi][nj], af[mi], b0, b1);
        }
#pragma unroll
        for (int mi = 0; mi < 2; mi++) {            // Al fragments
            int rb = wm * 32 + mi * 16;
            af[mi][0] = *(const unsigned*)&Al[(rb + g) * LDK + 2 * t];
            af[mi][1] = *(const unsigned*)&Al[(rb + g + 8) * LDK + 2 * t];
            af[mi][2] = *(const unsigned*)&Al[(rb + g) * LDK + 2 * t + 8];
            af[mi][3] = *(const unsigned*)&Al[(rb + g + 8) * LDK + 2 * t + 8];
        }
#pragma unroll
        for (int nj = 0; nj < 4; nj++) {            // Al * Wh
            int cb = wn * 32 + nj * 8 + g;
            unsigned b0 = *(const unsigned*)&Bh[cb * LDK + 2 * t];
            unsigned b1 = *(const unsigned*)&Bh[cb * LDK + 2 * t + 8];
#pragma unroll
            for (int mi = 0; mi < 2; mi++) mma16816(acc[mi][nj], af[mi], b0, b1);
        }
    }

#pragma unroll
    for (int mi = 0; mi < 2; mi++)
#pragma unroll
        for (int nj = 0; nj < 4; nj++) {
            int col = n0 + wn * 32 + nj * 8 + 2 * t;
            int r = m0 + wm * 32 + mi * 16 + g;
            if (col < PDIM) {            // col even, PDIM even -> col+1 < PDIM
                float b0v = bp[col], b1v = bp[col + 1];
                *(float2*)&g_params[r * PDIM + col] = make_float2(
                    clipf(acc[mi][nj][0] + b0v), clipf(acc[mi][nj][1] + b1v));
                *(float2*)&g_params[(r + 8) * PDIM + col] = make_float2(
                    clipf(acc[mi][nj][2] + b0v), clipf(acc[mi][nj][3] + b1v));
            } else if (col < 332) {      // h @ Wo_top, raw
                int cc = col - PDIM;
                *(float2*)&g_hWo[r * 64 + cc] =
                    make_float2(acc[mi][nj][0], acc[mi][nj][1]);
                *(float2*)&g_hWo[(r + 8) * 64 + cc] =
                    make_float2(acc[mi][nj][2], acc[mi][nj][3]);
            }
        }
}

// ---------------------------------------------------------------------------
// K3: per-sample addressing (both heads in parallel) + read_vec + M update
//     + fused output projection: out = clip(hWo + rv @ Wo_bot + bo).
// ---------------------------------------------------------------------------
__global__ __launch_bounds__(256) void k3_addr(
    const float* __restrict__ M,
    const float* __restrict__ w0p, const float* __restrict__ w1p,
    const float* __restrict__ Wo, const float* __restrict__ bo,
    float* __restrict__ out)
{
    __shared__ float Ms[128 * 65];
    __shared__ float psm[PDIM];
    __shared__ float ks[2][64], er[64], ad[64];
    __shared__ float wgs[2][128], wrs[128], wws[128];
    __shared__ float reds[2][4], redp[2][4];
    __shared__ float part[256];
    __shared__ float rvv[64];

    int b = blockIdx.x, tid = threadIdx.x;
    int h = tid >> 7, n = tid & 127;
    int lane = tid & 31, wid = tid >> 5, hw = wid & 3;

    const float4* M4 = (const float4*)(M + (size_t)b * NN * WW);
#pragma unroll
    for (int t = 0; t < 8; t++) {
        int idx4 = tid + t * 256;
        float4 v = M4[idx4];
        int r = idx4 >> 4, w0 = (idx4 & 15) * 4;
        float* p = &Ms[r * 65 + w0];
        p[0] = v.x; p[1] = v.y; p[2] = v.z; p[3] = v.w;
    }
    for (int i = tid; i < PDIM; i += 256) psm[i] = g_params[b * PDIM + i];
    __syncthreads();

    float s = 0.0f;
#pragma unroll
    for (int w = 0; w < 64; w++) { float m = Ms[n * 65 + w]; s += m * m; }
    float minv = rsqrtf(fmaxf(s, EPSV));

    if (tid < 64)                      er[tid] = sigf(psm[2 * NPH + tid]);
    else if (tid >= 128 && tid < 192)  ad[tid - 128] = tanhf(psm[2 * NPH + 64 + (tid - 128)]);

    int off = h * NPH;
    if (n < 64) ks[h][n] = tanhf(psm[off + n]);
    __syncthreads();

    float sk = 0.0f;
#pragma unroll
    for (int w = 0; w < 64; w++) sk += ks[h][w] * ks[h][w];
    float kninv = rsqrtf(fmaxf(sk, EPSV));
    float beta = softplusf(psm[off + 64]);
    float g = sigf(psm[off + 65]);
    float e0 = psm[off + 66], e1 = psm[off + 67], e2 = psm[off + 68];
    float mx3 = fmaxf(e0, fmaxf(e1, e2));
    float x0 = expf(e0 - mx3), x1 = expf(e1 - mx3), x2 = expf(e2 - mx3);
    float sinv = 1.0f / (x0 + x1 + x2);
    float s0 = x0 * sinv, s1 = x1 * sinv, s2 = x2 * sinv;
    float gamma = softplusf(psm[off + 69]) + 1.0f;

    float dot = 0.0f;
#pragma unroll
    for (int w = 0; w < 64; w++) dot += ks[h][w] * Ms[n * 65 + w];
    float v = beta * (-dot * kninv * minv);

    // |v| <= softplus(20) ~ 20 -> exp safe in fp32, no max pass needed
    float e = expf(v);
    float ssum = e;
#pragma unroll
    for (int o = 16; o; o >>= 1) ssum += __shfl_xor_sync(0xffffffffu, ssum, o);
    if (lane == 0) reds[h][hw] = ssum;
    __syncthreads();
    ssum = reds[h][0] + reds[h][1] + reds[h][2] + reds[h][3];
    float wc = e / ssum;

    const float* prev = h ? w1p : w0p;
    float wg = g * wc + (1.0f - g) * prev[b * 128 + n];
    wgs[h][n] = wg;
    __syncthreads();

    float w_ = s0 * wg + s1 * wgs[h][(n + 127) & 127] + s2 * wgs[h][(n + 1) & 127];
    float wsh = exp2f(gamma * log2f(w_));    // w_ >= 0; w_==0 -> 0
    float s2sum = wsh;
#pragma unroll
    for (int o = 16; o; o >>= 1) s2sum += __shfl_xor_sync(0xffffffffu, s2sum, o);
    if (lane == 0) redp[h][hw] = s2sum;
    __syncthreads();
    s2sum = redp[h][0] + redp[h][1] + redp[h][2] + redp[h][3];
    float wf = wsh / s2sum;

    if (h == 0) { wrs[n] = wf; out[O_WR + (size_t)b * 128 + n] = wf; }
    else        { wws[n] = wf; out[O_WW + (size_t)b * 128 + n] = wf; }
    __syncthreads();

    // read_vec: 4-way split over n
    {
        int w = tid & 63, q = tid >> 6;
        float r = 0.0f;
#pragma unroll
        for (int i = 0; i < 32; i++) {
            int nn = q * 32 + i;
            r += wrs[nn] * Ms[nn * 65 + w];
        }
        part[tid] = r;
        __syncthreads();
        if (tid < 64) {
            float rv = part[tid] + part[64 + tid] + part[128 + tid] + part[192 + tid];
            out[O_RV + (size_t)b * 64 + tid] = rv;
            rvv[tid] = rv;
        }
    }
    __syncthreads();

    // fused output projection: out = clip(hWo + rv @ Wo_bot + bo)
    {
        int c = tid & 63, q = tid >> 6;
        float a = 0.0f;
#pragma unroll
        for (int i = 0; i < 16; i++) {
            int k = q * 16 + i;
            a += rvv[k] * __ldg(&Wo[(256 + k) * 64 + c]);
        }
        part[tid] = a;
        __syncthreads();
        if (tid < 64)
            out[O_OUT + (size_t)b * 64 + tid] =
                clipf(part[tid] + part[64 + tid] + part[128 + tid] + part[192 + tid]
                      + g_hWo[b * 64 + tid] + bo[tid]);
    }

    // M update (no sync needed: uses wws/er/ad, all ready)
    float4* Mo = (float4*)(out + O_M + (size_t)b * NN * WW);
#pragma unroll
    for (int t = 0; t < 8; t++) {
        int idx4 = tid + t * 256;
        int r = idx4 >> 4, w0 = (idx4 & 15) * 4;
        float wn = wws[r];
        const float* p = &Ms[r * 65 + w0];
        float4 v4;
        v4.x = p[0] * (1.0f - wn * er[w0 + 0]) + wn * ad[w0 + 0];
        v4.y = p[1] * (1.0f - wn * er[w0 + 1]) + wn * ad[w0 + 1];
        v4.z = p[2] * (1.0f - wn * er[w0 + 2]) + wn * ad[w0 + 2];
        v4.w = p[3] * (1.0f - wn * er[w0 + 3]) + wn * ad[w0 + 3];
        Mo[idx4] = v4;
    }
}

// ---------------------------------------------------------------------------
extern "C" void kernel_launch(void* const* d_in, const int* in_sizes, int n_in,
                              void* d_out, int out_size)
{
    const float* x   = (const float*)d_in[0];
    const float* h0  = (const float*)d_in[1];
    const float* c0  = (const float*)d_in[2];
    const float* rv0 = (const float*)d_in[3];
    const float* w0p = (const float*)d_in[4];
    const float* w1p = (const float*)d_in[5];
    const float* M   = (const float*)d_in[6];
    const float* Wk  = (const float*)d_in[7];
    const float* Wr  = (const float*)d_in[8];
    const float* bl  = (const float*)d_in[9];
    const float* Wp  = (const float*)d_in[10];
    const float* bp  = (const float*)d_in[11];
    const float* Wo  = (const float*)d_in[12];
    const float* bo  = (const float*)d_in[13];
    float* out = (float*)d_out;

    k0_act<<<BB * KD / 1024, 1024>>>(x, rv0, h0);
    k0_wt<<<dim3(32, 12), 256>>>(Wk, Wr);
    k0_wp<<<dim3(12, 8), 256>>>(Wp, Wo);
    k1_gemm<<<dim3(32, 8), 256>>>();
    k2a_gates<<<BB * UU / 1024, 1024>>>(c0, bl, out);
    k2b_gemm<<<dim3(64, 3), 256>>>(bp);
    k3_addr<<<BB, 256>>>(M, w0p, w1p, Wo, bo, out);
}